// round 8
// baseline (speedup 1.0000x reference)
#include <cuda_runtime.h>
#include <cuda_fp16.h>
#include <cstdint>

#define NB 16384
#define NKEY 64
#define ND 128
#define NU 128
#define NM 32
#define TB 64             // rows per CTA (2 CTAs co-resident per SM)
#define NCH 33            // 32 weight chunks (K=128) + 1 bias chunk (K=32, zero-padded)
#define CHB 32768         // bytes per fragment-ordered fp16 B chunk

__device__ __align__(16) unsigned char g_Bf[NCH * CHB];

// ---------------------------------------------------------------------------
// prep_b: B chunks -> fp16 fragment order, nf-paired uint4 layout, 1/MODES
// folded in. uint4 at ((ksn*8 + jp)*32 + l)*16 holds, for lane l {g=l>>2,t=l&3},
// k0 = 16*ksn + 2*t, n_e = jp*16+g, n_o = n_e+8:
//   { h2(B[k0][n_e],B[k0+1][n_e]), h2(B[k0+8][n_e],B[k0+9][n_e]),
//     h2(B[k0][n_o],B[k0+1][n_o]), h2(B[k0+8][n_o],B[k0+9][n_o]) } * (1/32)
// ---------------------------------------------------------------------------
__global__ __launch_bounds__(256) void prep_b(const float* __restrict__ kernels,
                                              const float* __restrict__ biases)
{
    __shared__ float Bs[32 * 129];
    const int pb = blockIdx.x;
    const int c = pb >> 2, p = pb & 3;
    const int tid = threadIdx.x;
    const float sc = 1.0f / 32.0f;

    for (int i = tid; i < 32 * 128; i += 256) {
        const int kl = i >> 7, n = i & 127, k = p * 32 + kl;
        float v;
        if (c < 32) v = kernels[(size_t)c * 16384 + (size_t)k * 128 + n];
        else        v = (p == 0) ? biases[k * 128 + n] : 0.f;
        Bs[kl * 129 + n] = v * sc;
    }
    __syncthreads();

    #pragma unroll
    for (int it = 0; it < 2; it++) {
        const int i = it * 256 + tid;
        const int ksn = 2 * p + (i >> 8);
        const int rest = i & 255;
        const int jp = rest >> 5, l = rest & 31;
        const int g = l >> 2, t = l & 3;
        const int kl = 16 * (i >> 8) + 2 * t;
        const int ne = jp * 16 + g, no = ne + 8;
        __half2 h0 = __floats2half2_rn(Bs[kl * 129 + ne], Bs[(kl + 1) * 129 + ne]);
        __half2 h1 = __floats2half2_rn(Bs[(kl + 8) * 129 + ne], Bs[(kl + 9) * 129 + ne]);
        __half2 h2v = __floats2half2_rn(Bs[kl * 129 + no], Bs[(kl + 1) * 129 + no]);
        __half2 h3 = __floats2half2_rn(Bs[(kl + 8) * 129 + no], Bs[(kl + 9) * 129 + no]);
        uint4 wv;
        wv.x = *(uint32_t*)&h0;  wv.y = *(uint32_t*)&h1;
        wv.z = *(uint32_t*)&h2v; wv.w = *(uint32_t*)&h3;
        *(uint4*)(g_Bf + (size_t)c * CHB +
                  (size_t)((ksn * 8 + jp) * 32 + l) * 16) = wv;
    }
}

// ---------------------------------------------------------------------------
// mma_kernel: 256 CTAs x 256 threads (8 warps, warp tile 16x64, 64 rows/CTA).
// 2 CTAs co-resident per SM so one CTA's compute fills the other's barrier
// bubbles. A in registers (HMUL2 build); B: 3-stage cp.async pipeline.
// ---------------------------------------------------------------------------
#define SIM_OFF 0                       // 64*33 f32 = 8448
#define B_OFF   8448                    // 3 x 32768 = 98304
#define SC_OFF  (B_OFF + 2 * 32768)     // sim scratch inside B stage 2
#define SMEM_BYTES 106752

__device__ __forceinline__ void mma16816(float* c, const uint32_t* a,
                                         uint32_t b0, uint32_t b1) {
    asm volatile(
        "mma.sync.aligned.m16n8k16.row.col.f32.f16.f16.f32 "
        "{%0,%1,%2,%3}, {%4,%5,%6,%7}, {%8,%9}, {%0,%1,%2,%3};"
        : "+f"(c[0]), "+f"(c[1]), "+f"(c[2]), "+f"(c[3])
        : "r"(a[0]), "r"(a[1]), "r"(a[2]), "r"(a[3]), "r"(b0), "r"(b1));
}

__global__ __launch_bounds__(256, 2) void mma_kernel(const float* __restrict__ x,
                                                     const float* __restrict__ key,
                                                     const float* __restrict__ sens,
                                                     const float* __restrict__ keys_map,
                                                     float* __restrict__ out)
{
    extern __shared__ __align__(16) unsigned char sm[];
    float* simS = (float*)(sm + SIM_OFF);    // [row][m] stride 33

    uint32_t smb;
    asm("{ .reg .u64 t; cvta.to.shared.u64 t, %1; cvt.u32.u64 %0, t; }"
        : "=r"(smb) : "l"(sm));
    uint64_t gb;
    {
        const unsigned char* p = g_Bf;
        asm("cvta.to.global.u64 %0, %1;" : "=l"(gb) : "l"(p));
    }

    const int tid = threadIdx.x;
    const int l = tid & 31, w = tid >> 5;
    const int g = l >> 2, t = l & 3;
    const int rg = w >> 1, cg = w & 1;               // warp tile 16x64
    const int row0 = blockIdx.x * TB;
    const int r0 = rg * 16 + g;                      // this thread's 2 A rows (0..63)
    const int r1 = r0 + 8;

    // ---- cp.async B chunks 0,1 into stages 0,1 ----
    #pragma unroll
    for (int cc = 0; cc < 2; cc++) {
        const uint32_t dst = smb + B_OFF + cc * 32768;
        const uint64_t src = gb + (uint64_t)cc * CHB;
        #pragma unroll
        for (int j = 0; j < 8; j++) {
            const uint32_t off = (uint32_t)(j * 256 + tid) * 16;
            asm volatile("cp.async.cg.shared.global [%0], [%1], 16;"
                         :: "r"(dst + off), "l"(src + off));
        }
        asm volatile("cp.async.commit_group;");
    }

    // ---- x -> registers as half2, fragment slot order (2 rows) ----
    __half2 xh[2][8][2];
    {
        const float* x0 = x + (size_t)(row0 + r0) * ND;
        const float* x1 = x + (size_t)(row0 + r1) * ND;
        #pragma unroll
        for (int j = 0; j < 8; j++) {
            const int k0 = j * 16 + 2 * t;
            float2 v0 = __ldg((const float2*)(x0 + k0));
            float2 v1 = __ldg((const float2*)(x0 + k0 + 8));
            float2 v2 = __ldg((const float2*)(x1 + k0));
            float2 v3 = __ldg((const float2*)(x1 + k0 + 8));
            xh[0][j][0] = __floats2half2_rn(v0.x, v0.y);
            xh[0][j][1] = __floats2half2_rn(v1.x, v1.y);
            xh[1][j][0] = __floats2half2_rn(v2.x, v2.y);
            xh[1][j][1] = __floats2half2_rn(v3.x, v3.y);
        }
    }

    // ---- compute sim for this CTA's 64 rows (warp w -> rows w*8..w*8+7) ----
    {
        float* kmS = (float*)(sm + SC_OFF);          // [32][65] = 8320 B
        float* ssS = kmS + 32 * 65;                  // [32]
        float* ksS = ssS + 32;                       // [64][64] = 16384 B
        for (int i = tid; i < NM * NKEY; i += 256)
            kmS[(i >> 6) * 65 + (i & 63)] = keys_map[i];
        for (int i = tid; i < TB * NKEY; i += 256)
            ksS[i] = key[(size_t)row0 * NKEY + i];
        if (tid < NM) ssS[tid] = sens[tid];
        __syncthreads();

        const int m = l;
        #pragma unroll 1
        for (int i = 0; i < 8; i++) {
            const int r = w * 8 + i;
            float d2 = 0.f;
            #pragma unroll
            for (int k = 0; k < NKEY; k++) {
                const float df = ksS[r * 64 + k] - kmS[m * 65 + k];
                d2 = fmaf(df, df, d2);
            }
            const float lg = ssS[m] / (sqrtf(d2) + 1.0f);
            float mx = lg;
            #pragma unroll
            for (int o = 16; o > 0; o >>= 1)
                mx = fmaxf(mx, __shfl_xor_sync(0xFFFFFFFFu, mx, o));
            const float e = __expf(lg - mx);
            float s = e;
            #pragma unroll
            for (int o = 16; o > 0; o >>= 1)
                s += __shfl_xor_sync(0xFFFFFFFFu, s, o);
            simS[r * 33 + m] = e / s;
        }
    }

    // chunk 0 ready (chunk 1 may still be in flight); also fences scratch reads
    asm volatile("cp.async.wait_group 1;");
    __syncthreads();

    float acc[8][4];
    #pragma unroll
    for (int nf = 0; nf < 8; nf++)
        #pragma unroll
        for (int i = 0; i < 4; i++) acc[nf][i] = 0.f;

    // ---- mainloop over the 32 weight chunks (stage = chunk % 3) ----
    #pragma unroll 1
    for (int c = 0; c < 32; c++) {
        if (c + 2 < NCH) {   // prefetch chunk c+2 into stage (c+2)%3
            const int st = (c + 2) % 3;
            const uint32_t dst = smb + B_OFF + st * 32768;
            const uint64_t src = gb + (uint64_t)(c + 2) * CHB;
            #pragma unroll
            for (int j = 0; j < 8; j++) {
                const uint32_t off = (uint32_t)(j * 256 + tid) * 16;
                asm volatile("cp.async.cg.shared.global [%0], [%1], 16;"
                             :: "r"(dst + off), "l"(src + off));
            }
            asm volatile("cp.async.commit_group;");
        }

        const __half2 sh0 = __float2half2_rn(simS[r0 * 33 + c]);
        const __half2 sh1 = __float2half2_rn(simS[r1 * 33 + c]);

        const uint4* bbb = (const uint4*)(sm + B_OFF + (c % 3) * 32768);
        #pragma unroll
        for (int ksn = 0; ksn < 8; ksn++) {
            __half2 f;
            uint32_t a0[4];
            f = __hmul2(sh0, xh[0][ksn][0]); a0[0] = *(uint32_t*)&f;
            f = __hmul2(sh1, xh[1][ksn][0]); a0[1] = *(uint32_t*)&f;
            f = __hmul2(sh0, xh[0][ksn][1]); a0[2] = *(uint32_t*)&f;
            f = __hmul2(sh1, xh[1][ksn][1]); a0[3] = *(uint32_t*)&f;
            #pragma unroll
            for (int nf2 = 0; nf2 < 4; nf2++) {
                uint4 Bp = bbb[(ksn * 8 + cg * 4 + nf2) * 32 + l];
                mma16816(acc[2*nf2+0], a0, Bp.x, Bp.y);
                mma16816(acc[2*nf2+1], a0, Bp.z, Bp.w);
            }
        }

        // ensure chunk c+1 has landed; barrier publishes + protects stage reuse
        if (c + 2 < NCH) { asm volatile("cp.async.wait_group 1;"); }
        else             { asm volatile("cp.async.wait_group 0;"); }
        __syncthreads();
    }

    // ---- peeled bias chunk (c=32, stage 2): A = sim over k<32 ----
    {
        const uint4* bbb = (const uint4*)(sm + B_OFF + 2 * 32768);
        #pragma unroll
        for (int ksn = 0; ksn < 2; ksn++) {
            const int k0 = ksn * 16 + 2 * t;
            __half2 f;
            uint32_t a0[4];
            f = __floats2half2_rn(simS[r0*33 + k0],   simS[r0*33 + k0+1]); a0[0] = *(uint32_t*)&f;
            f = __floats2half2_rn(simS[r1*33 + k0],   simS[r1*33 + k0+1]); a0[1] = *(uint32_t*)&f;
            f = __floats2half2_rn(simS[r0*33 + k0+8], simS[r0*33 + k0+9]); a0[2] = *(uint32_t*)&f;
            f = __floats2half2_rn(simS[r1*33 + k0+8], simS[r1*33 + k0+9]); a0[3] = *(uint32_t*)&f;
            #pragma unroll
            for (int nf2 = 0; nf2 < 4; nf2++) {
                uint4 Bp = bbb[(ksn * 8 + cg * 4 + nf2) * 32 + l];
                mma16816(acc[2*nf2+0], a0, Bp.x, Bp.y);
                mma16816(acc[2*nf2+1], a0, Bp.z, Bp.w);
            }
        }
    }

    // ---- epilogue (1/32 already folded into B) ----
    {
        const int ra = row0 + r0, rb2 = row0 + r1;
        #pragma unroll
        for (int nf = 0; nf < 8; nf++) {
            const int col = cg * 64 + nf * 8 + 2 * t;
            float2 v0, v1;
            v0.x = acc[nf][0]; v0.y = acc[nf][1];
            v1.x = acc[nf][2]; v1.y = acc[nf][3];
            *(float2*)&out[(size_t)ra * NU + col] = v0;
            *(float2*)&out[(size_t)rb2 * NU + col] = v1;
        }
    }
}

// ---------------------------------------------------------------------------
extern "C" void kernel_launch(void* const* d_in, const int* in_sizes, int n_in,
                              void* d_out, int out_size)
{
    const float *key = 0, *x = 0, *sens = 0, *keys_map = 0, *kernels = 0, *biases = 0;
    for (int i = 0; i < n_in; i++) {
        switch (in_sizes[i]) {
            case NB * NKEY:    key      = (const float*)d_in[i]; break;
            case NB * ND:      x        = (const float*)d_in[i]; break;
            case NM:           sens     = (const float*)d_in[i]; break;
            case NM * NKEY:    keys_map = (const float*)d_in[i]; break;
            case NM * ND * NU: kernels  = (const float*)d_in[i]; break;
            case NM * NU:      biases   = (const float*)d_in[i]; break;
            default: break;
        }
    }
    float* out = (float*)d_out;

    cudaFuncSetAttribute(mma_kernel, cudaFuncAttributeMaxDynamicSharedMemorySize,
                         SMEM_BYTES);

    prep_b<<<NCH * 4, 256>>>(kernels, biases);
    mma_kernel<<<NB / TB, 256, SMEM_BYTES>>>(x, key, sens, keys_map, out);
}

// round 9
// speedup vs baseline: 1.1920x; 1.1920x over previous
#include <cuda_runtime.h>
#include <cuda_fp16.h>
#include <cstdint>

#define NB 16384
#define NKEY 64
#define ND 128
#define NU 128
#define NM 32
#define TB 128
#define NCH 33            // 32 weight chunks (K=128) + 1 bias chunk (K=32, zero-padded)
#define CHB 32768         // bytes per fragment-ordered fp16 B chunk
#define NSTAGE 4

__device__ __align__(16) unsigned char g_Bf[NCH * CHB];

// ---------------------------------------------------------------------------
// prep_b: B chunks -> fp16 fragment order, nf-paired uint4 layout, 1/MODES
// folded in. uint4 at ((ksn*8 + jp)*32 + l)*16 holds, for lane l {g=l>>2,t=l&3},
// k0 = 16*ksn + 2*t, n_e = jp*16+g, n_o = n_e+8:
//   { h2(B[k0][n_e],B[k0+1][n_e]), h2(B[k0+8][n_e],B[k0+9][n_e]),
//     h2(B[k0][n_o],B[k0+1][n_o]), h2(B[k0+8][n_o],B[k0+9][n_o]) } * (1/32)
// ---------------------------------------------------------------------------
__global__ __launch_bounds__(256) void prep_b(const float* __restrict__ kernels,
                                              const float* __restrict__ biases)
{
    __shared__ float Bs[32 * 129];
    const int pb = blockIdx.x;
    const int c = pb >> 2, p = pb & 3;
    const int tid = threadIdx.x;
    const float sc = 1.0f / 32.0f;

    for (int i = tid; i < 32 * 128; i += 256) {
        const int kl = i >> 7, n = i & 127, k = p * 32 + kl;
        float v;
        if (c < 32) v = kernels[(size_t)c * 16384 + (size_t)k * 128 + n];
        else        v = (p == 0) ? biases[k * 128 + n] : 0.f;
        Bs[kl * 129 + n] = v * sc;
    }
    __syncthreads();

    #pragma unroll
    for (int it = 0; it < 2; it++) {
        const int i = it * 256 + tid;
        const int ksn = 2 * p + (i >> 8);
        const int rest = i & 255;
        const int jp = rest >> 5, l = rest & 31;
        const int g = l >> 2, t = l & 3;
        const int kl = 16 * (i >> 8) + 2 * t;
        const int ne = jp * 16 + g, no = ne + 8;
        __half2 h0 = __floats2half2_rn(Bs[kl * 129 + ne], Bs[(kl + 1) * 129 + ne]);
        __half2 h1 = __floats2half2_rn(Bs[(kl + 8) * 129 + ne], Bs[(kl + 9) * 129 + ne]);
        __half2 h2v = __floats2half2_rn(Bs[kl * 129 + no], Bs[(kl + 1) * 129 + no]);
        __half2 h3 = __floats2half2_rn(Bs[(kl + 8) * 129 + no], Bs[(kl + 9) * 129 + no]);
        uint4 wv;
        wv.x = *(uint32_t*)&h0;  wv.y = *(uint32_t*)&h1;
        wv.z = *(uint32_t*)&h2v; wv.w = *(uint32_t*)&h3;
        *(uint4*)(g_Bf + (size_t)c * CHB +
                  (size_t)((ksn * 8 + jp) * 32 + l) * 16) = wv;
    }
}

// ---------------------------------------------------------------------------
// mbarrier helpers (sm_90 PTX, safe under compute_103)
// ---------------------------------------------------------------------------
__device__ __forceinline__ void mbar_init(uint32_t mbar, uint32_t cnt) {
    asm volatile("mbarrier.init.shared.b64 [%0], %1;" :: "r"(mbar), "r"(cnt) : "memory");
}
__device__ __forceinline__ void mbar_arrive(uint32_t mbar) {
    asm volatile("mbarrier.arrive.shared.b64 _, [%0];" :: "r"(mbar) : "memory");
}
__device__ __forceinline__ void mbar_expect_tx(uint32_t mbar, uint32_t bytes) {
    asm volatile("mbarrier.arrive.expect_tx.shared.b64 _, [%0], %1;"
                 :: "r"(mbar), "r"(bytes) : "memory");
}
__device__ __forceinline__ void mbar_wait(uint32_t mbar, uint32_t parity) {
    asm volatile(
        "{\n\t.reg .pred P;\n\t"
        "W%=:\n\t"
        "mbarrier.try_wait.parity.acquire.cta.shared::cta.b64 P, [%0], %1, 0x989680;\n\t"
        "@!P bra W%=;\n\t}"
        :: "r"(mbar), "r"(parity) : "memory");
}
__device__ __forceinline__ void bulk_copy(uint32_t dst, uint64_t src, uint32_t bytes,
                                          uint32_t mbar) {
    asm volatile(
        "cp.async.bulk.shared::cluster.global.mbarrier::complete_tx::bytes "
        "[%0], [%1], %2, [%3];"
        :: "r"(dst), "l"(src), "r"(bytes), "r"(mbar) : "memory");
}

// ---------------------------------------------------------------------------
// mma_kernel: 128 CTAs x 288 threads.
//   warps 0-7: consumers (warp tile 32x64, register A via HMUL2)
//   warp 8:    producer (cp.async.bulk B chunks through 4-stage mbarrier ring)
// NO __syncthreads in the mainloop — warps are fully decoupled.
// ---------------------------------------------------------------------------
#define SIM_OFF 0                       // 128*33 f32 = 16896
#define MB_OFF  16896                   // full[4] @ +0, empty[4] @ +32
#define KM_OFF  17024                   // 32*65 f32 + 32 f32 = 8448
#define KS_OFF  25472                   // 128*64 f32 = 32768 (prologue scratch)
#define B_OFF   58368                   // 4 x 32768
#define SMEM_BYTES 189440

__device__ __forceinline__ void mma16816(float* c, const uint32_t* a,
                                         uint32_t b0, uint32_t b1) {
    asm volatile(
        "mma.sync.aligned.m16n8k16.row.col.f32.f16.f16.f32 "
        "{%0,%1,%2,%3}, {%4,%5,%6,%7}, {%8,%9}, {%0,%1,%2,%3};"
        : "+f"(c[0]), "+f"(c[1]), "+f"(c[2]), "+f"(c[3])
        : "r"(a[0]), "r"(a[1]), "r"(a[2]), "r"(a[3]), "r"(b0), "r"(b1));
}

__global__ __launch_bounds__(288, 1) void mma_kernel(const float* __restrict__ x,
                                                     const float* __restrict__ key,
                                                     const float* __restrict__ sens,
                                                     const float* __restrict__ keys_map,
                                                     float* __restrict__ out)
{
    extern __shared__ __align__(16) unsigned char sm[];
    float* simS = (float*)(sm + SIM_OFF);    // [row][m] stride 33

    uint32_t smb;
    asm("{ .reg .u64 t; cvta.to.shared.u64 t, %1; cvt.u32.u64 %0, t; }"
        : "=r"(smb) : "l"(sm));
    uint64_t gb;
    {
        const unsigned char* p = g_Bf;
        asm("cvta.to.global.u64 %0, %1;" : "=l"(gb) : "l"(p));
    }

    const int tid = threadIdx.x;
    const int l = tid & 31, w = tid >> 5;
    const int g = l >> 2, t = l & 3;
    const int row0 = blockIdx.x * TB;

    const uint32_t mb_full  = smb + MB_OFF;       // +8*s
    const uint32_t mb_empty = smb + MB_OFF + 32;  // +8*s

    // ---- init mbarriers + stage prologue scratch ----
    if (tid == 0) {
        #pragma unroll
        for (int s = 0; s < NSTAGE; s++) {
            mbar_init(mb_full + 8 * s, 1);
            mbar_init(mb_empty + 8 * s, 8);
        }
    }
    {
        float* kmS = (float*)(sm + KM_OFF);
        float* ssS = kmS + 32 * 65;
        float* ksS = (float*)(sm + KS_OFF);
        for (int i = tid; i < NM * NKEY; i += 288)
            kmS[(i >> 6) * 65 + (i & 63)] = keys_map[i];
        for (int i = tid; i < TB * NKEY; i += 288)
            ksS[i] = key[(size_t)row0 * NKEY + i];
        if (tid < NM) ssS[tid] = sens[tid];
    }
    __syncthreads();   // mbarriers + scratch visible; last CTA-wide barrier

    if (w == 8) {
        // ------------------------------ producer ------------------------------
        if (l == 0) {
            #pragma unroll 1
            for (int c = 0; c < NCH; c++) {
                const int s = c & 3;
                const uint32_t u = (uint32_t)(c >> 2);
                mbar_wait(mb_empty + 8 * s, (u & 1u) ^ 1u);   // first use: immediate
                mbar_expect_tx(mb_full + 8 * s, CHB);
                bulk_copy(smb + B_OFF + s * 32768, gb + (uint64_t)c * CHB,
                          CHB, mb_full + 8 * s);
            }
        }
        return;
    }

    // ------------------------------ consumers ------------------------------
    const int rg = w >> 1, cg = w & 1;               // warp tile 32x64
    const int r00 = rg * 32 + g;
    const int r01 = r00 + 8, r10 = r00 + 16, r11 = r00 + 24;

    // ---- x -> registers as half2, fragment slot order (4 rows) ----
    __half2 xh[4][8][2];
    {
        const int rows[4] = {r00, r01, r10, r11};
        #pragma unroll
        for (int i = 0; i < 4; i++) {
            const float* xp = x + (size_t)(row0 + rows[i]) * ND;
            #pragma unroll
            for (int j = 0; j < 8; j++) {
                const int k0 = j * 16 + 2 * t;
                float2 v0 = __ldg((const float2*)(xp + k0));
                float2 v1 = __ldg((const float2*)(xp + k0 + 8));
                xh[i][j][0] = __floats2half2_rn(v0.x, v0.y);
                xh[i][j][1] = __floats2half2_rn(v1.x, v1.y);
            }
        }
    }

    // ---- sim for this CTA's 128 rows (warp w -> rows w*16..w*16+15) ----
    {
        const float* kmS = (const float*)(sm + KM_OFF);
        const float* ssS = kmS + 32 * 65;
        const float* ksS = (const float*)(sm + KS_OFF);
        const int m = l;
        #pragma unroll 1
        for (int i = 0; i < 16; i++) {
            const int r = w * 16 + i;
            float d2 = 0.f;
            #pragma unroll
            for (int k = 0; k < NKEY; k++) {
                const float df = ksS[r * 64 + k] - kmS[m * 65 + k];
                d2 = fmaf(df, df, d2);
            }
            const float lg = ssS[m] / (sqrtf(d2) + 1.0f);
            float mx = lg;
            #pragma unroll
            for (int o = 16; o > 0; o >>= 1)
                mx = fmaxf(mx, __shfl_xor_sync(0xFFFFFFFFu, mx, o));
            const float e = __expf(lg - mx);
            float s = e;
            #pragma unroll
            for (int o = 16; o > 0; o >>= 1)
                s += __shfl_xor_sync(0xFFFFFFFFu, s, o);
            simS[r * 33 + m] = e / s;
        }
    }
    // consumer-only barrier (producer is busy in its loop)
    asm volatile("bar.sync 1, 256;" ::: "memory");

    float acc[2][8][4];
    #pragma unroll
    for (int mf = 0; mf < 2; mf++)
        #pragma unroll
        for (int nf = 0; nf < 8; nf++)
            #pragma unroll
            for (int i = 0; i < 4; i++) acc[mf][nf][i] = 0.f;

    // ---- mainloop: 32 weight chunks, no CTA-wide barriers ----
    #pragma unroll 1
    for (int c = 0; c < 32; c++) {
        const int s = c & 3;
        const uint32_t u = (uint32_t)(c >> 2);
        mbar_wait(mb_full + 8 * s, u & 1u);

        const __half2 sh0 = __float2half2_rn(simS[r00 * 33 + c]);
        const __half2 sh1 = __float2half2_rn(simS[r01 * 33 + c]);
        const __half2 sh2 = __float2half2_rn(simS[r10 * 33 + c]);
        const __half2 sh3 = __float2half2_rn(simS[r11 * 33 + c]);

        const uint4* bbb = (const uint4*)(sm + B_OFF + s * 32768);
        #pragma unroll
        for (int ksn = 0; ksn < 8; ksn++) {
            __half2 f;
            uint32_t a0[4], a1[4];
            f = __hmul2(sh0, xh[0][ksn][0]); a0[0] = *(uint32_t*)&f;
            f = __hmul2(sh1, xh[1][ksn][0]); a0[1] = *(uint32_t*)&f;
            f = __hmul2(sh0, xh[0][ksn][1]); a0[2] = *(uint32_t*)&f;
            f = __hmul2(sh1, xh[1][ksn][1]); a0[3] = *(uint32_t*)&f;
            f = __hmul2(sh2, xh[2][ksn][0]); a1[0] = *(uint32_t*)&f;
            f = __hmul2(sh3, xh[3][ksn][0]); a1[1] = *(uint32_t*)&f;
            f = __hmul2(sh2, xh[2][ksn][1]); a1[2] = *(uint32_t*)&f;
            f = __hmul2(sh3, xh[3][ksn][1]); a1[3] = *(uint32_t*)&f;
            #pragma unroll
            for (int nf2 = 0; nf2 < 4; nf2++) {
                uint4 Bp = bbb[(ksn * 8 + cg * 4 + nf2) * 32 + l];
                mma16816(acc[0][2*nf2+0], a0, Bp.x, Bp.y);
                mma16816(acc[1][2*nf2+0], a1, Bp.x, Bp.y);
                mma16816(acc[0][2*nf2+1], a0, Bp.z, Bp.w);
                mma16816(acc[1][2*nf2+1], a1, Bp.z, Bp.w);
            }
        }

        __syncwarp();
        if (l == 0) mbar_arrive(mb_empty + 8 * s);   // this warp done with stage s
    }

    // ---- bias chunk c=32 (stage 0): A = sim over k<32 ----
    {
        const int s = 0;
        mbar_wait(mb_full + 8 * s, (32 >> 2) & 1u);  // u=8 -> parity 0
        const uint4* bbb = (const uint4*)(sm + B_OFF + s * 32768);
        #pragma unroll
        for (int ksn = 0; ksn < 2; ksn++) {
            const int k0 = ksn * 16 + 2 * t;
            __half2 f;
            uint32_t a0[4], a1[4];
            f = __floats2half2_rn(simS[r00*33 + k0],   simS[r00*33 + k0+1]); a0[0] = *(uint32_t*)&f;
            f = __floats2half2_rn(simS[r01*33 + k0],   simS[r01*33 + k0+1]); a0[1] = *(uint32_t*)&f;
            f = __floats2half2_rn(simS[r00*33 + k0+8], simS[r00*33 + k0+9]); a0[2] = *(uint32_t*)&f;
            f = __floats2half2_rn(simS[r01*33 + k0+8], simS[r01*33 + k0+9]); a0[3] = *(uint32_t*)&f;
            f = __floats2half2_rn(simS[r10*33 + k0],   simS[r10*33 + k0+1]); a1[0] = *(uint32_t*)&f;
            f = __floats2half2_rn(simS[r11*33 + k0],   simS[r11*33 + k0+1]); a1[1] = *(uint32_t*)&f;
            f = __floats2half2_rn(simS[r10*33 + k0+8], simS[r10*33 + k0+9]); a1[2] = *(uint32_t*)&f;
            f = __floats2half2_rn(simS[r11*33 + k0+8], simS[r11*33 + k0+9]); a1[3] = *(uint32_t*)&f;
            #pragma unroll
            for (int nf2 = 0; nf2 < 4; nf2++) {
                uint4 Bp = bbb[(ksn * 8 + cg * 4 + nf2) * 32 + l];
                mma16816(acc[0][2*nf2+0], a0, Bp.x, Bp.y);
                mma16816(acc[1][2*nf2+0], a1, Bp.x, Bp.y);
                mma16816(acc[0][2*nf2+1], a0, Bp.z, Bp.w);
                mma16816(acc[1][2*nf2+1], a1, Bp.z, Bp.w);
            }
        }
    }

    // ---- epilogue (1/32 already folded into B) ----
    #pragma unroll
    for (int mf = 0; mf < 2; mf++) {
        const int r = row0 + rg * 32 + mf * 16 + g;
        #pragma unroll
        for (int nf = 0; nf < 8; nf++) {
            const int col = cg * 64 + nf * 8 + 2 * t;
            float2 v0, v1;
            v0.x = acc[mf][nf][0]; v0.y = acc[mf][nf][1];
            v1.x = acc[mf][nf][2]; v1.y = acc[mf][nf][3];
            *(float2*)&out[(size_t)r * NU + col] = v0;
            *(float2*)&out[(size_t)(r + 8) * NU + col] = v1;
        }
    }
}

// ---------------------------------------------------------------------------
extern "C" void kernel_launch(void* const* d_in, const int* in_sizes, int n_in,
                              void* d_out, int out_size)
{
    const float *key = 0, *x = 0, *sens = 0, *keys_map = 0, *kernels = 0, *biases = 0;
    for (int i = 0; i < n_in; i++) {
        switch (in_sizes[i]) {
            case NB * NKEY:    key      = (const float*)d_in[i]; break;
            case NB * ND:      x        = (const float*)d_in[i]; break;
            case NM:           sens     = (const float*)d_in[i]; break;
            case NM * NKEY:    keys_map = (const float*)d_in[i]; break;
            case NM * ND * NU: kernels  = (const float*)d_in[i]; break;
            case NM * NU:      biases   = (const float*)d_in[i]; break;
            default: break;
        }
    }
    float* out = (float*)d_out;

    cudaFuncSetAttribute(mma_kernel, cudaFuncAttributeMaxDynamicSharedMemorySize,
                         SMEM_BYTES);

    prep_b<<<NCH * 4, 256>>>(kernels, biases);
    mma_kernel<<<NB / TB, 288, SMEM_BYTES>>>(x, key, sens, keys_map, out);
}

// round 10
// speedup vs baseline: 1.2025x; 1.0088x over previous
#include <cuda_runtime.h>
#include <cuda_fp16.h>
#include <cstdint>

#define NB 16384
#define NKEY 64
#define ND 128
#define NU 128
#define NM 32
#define TB 128
#define NCH 33            // 32 weight chunks (K=128) + 1 bias chunk (K=32, zero-padded)
#define CHB 32768         // bytes per fragment-ordered fp16 B chunk
#define NSTAGE 4
#define NCONS 16          // consumer warps
#define NTHR (NCONS * 32 + 32)

__device__ __align__(16) unsigned char g_Bf[NCH * CHB];

// ---------------------------------------------------------------------------
// prep_b: B chunks -> fp16 fragment order, nf-paired uint4 layout, 1/MODES
// folded in. uint4 at ((ksn*8 + jp)*32 + l)*16 holds, for lane l {g=l>>2,t=l&3},
// k0 = 16*ksn + 2*t, n_e = jp*16+g, n_o = n_e+8:
//   { h2(B[k0][n_e],B[k0+1][n_e]), h2(B[k0+8][n_e],B[k0+9][n_e]),
//     h2(B[k0][n_o],B[k0+1][n_o]), h2(B[k0+8][n_o],B[k0+9][n_o]) } * (1/32)
// ---------------------------------------------------------------------------
__global__ __launch_bounds__(256) void prep_b(const float* __restrict__ kernels,
                                              const float* __restrict__ biases)
{
    __shared__ float Bs[32 * 129];
    const int pb = blockIdx.x;
    const int c = pb >> 2, p = pb & 3;
    const int tid = threadIdx.x;
    const float sc = 1.0f / 32.0f;

    for (int i = tid; i < 32 * 128; i += 256) {
        const int kl = i >> 7, n = i & 127, k = p * 32 + kl;
        float v;
        if (c < 32) v = kernels[(size_t)c * 16384 + (size_t)k * 128 + n];
        else        v = (p == 0) ? biases[k * 128 + n] : 0.f;
        Bs[kl * 129 + n] = v * sc;
    }
    __syncthreads();

    #pragma unroll
    for (int it = 0; it < 2; it++) {
        const int i = it * 256 + tid;
        const int ksn = 2 * p + (i >> 8);
        const int rest = i & 255;
        const int jp = rest >> 5, l = rest & 31;
        const int g = l >> 2, t = l & 3;
        const int kl = 16 * (i >> 8) + 2 * t;
        const int ne = jp * 16 + g, no = ne + 8;
        __half2 h0 = __floats2half2_rn(Bs[kl * 129 + ne], Bs[(kl + 1) * 129 + ne]);
        __half2 h1 = __floats2half2_rn(Bs[(kl + 8) * 129 + ne], Bs[(kl + 9) * 129 + ne]);
        __half2 h2v = __floats2half2_rn(Bs[kl * 129 + no], Bs[(kl + 1) * 129 + no]);
        __half2 h3 = __floats2half2_rn(Bs[(kl + 8) * 129 + no], Bs[(kl + 9) * 129 + no]);
        uint4 wv;
        wv.x = *(uint32_t*)&h0;  wv.y = *(uint32_t*)&h1;
        wv.z = *(uint32_t*)&h2v; wv.w = *(uint32_t*)&h3;
        *(uint4*)(g_Bf + (size_t)c * CHB +
                  (size_t)((ksn * 8 + jp) * 32 + l) * 16) = wv;
    }
}

// ---------------------------------------------------------------------------
// mbarrier helpers
// ---------------------------------------------------------------------------
__device__ __forceinline__ void mbar_init(uint32_t mbar, uint32_t cnt) {
    asm volatile("mbarrier.init.shared.b64 [%0], %1;" :: "r"(mbar), "r"(cnt) : "memory");
}
__device__ __forceinline__ void mbar_arrive(uint32_t mbar) {
    asm volatile("mbarrier.arrive.shared.b64 _, [%0];" :: "r"(mbar) : "memory");
}
__device__ __forceinline__ void mbar_expect_tx(uint32_t mbar, uint32_t bytes) {
    asm volatile("mbarrier.arrive.expect_tx.shared.b64 _, [%0], %1;"
                 :: "r"(mbar), "r"(bytes) : "memory");
}
__device__ __forceinline__ void mbar_wait(uint32_t mbar, uint32_t parity) {
    asm volatile(
        "{\n\t.reg .pred P;\n\t"
        "W%=:\n\t"
        "mbarrier.try_wait.parity.acquire.cta.shared::cta.b64 P, [%0], %1, 0x989680;\n\t"
        "@!P bra W%=;\n\t}"
        :: "r"(mbar), "r"(parity) : "memory");
}
__device__ __forceinline__ void bulk_copy(uint32_t dst, uint64_t src, uint32_t bytes,
                                          uint32_t mbar) {
    asm volatile(
        "cp.async.bulk.shared::cluster.global.mbarrier::complete_tx::bytes "
        "[%0], [%1], %2, [%3];"
        :: "r"(dst), "l"(src), "r"(bytes), "r"(mbar) : "memory");
}

// ---------------------------------------------------------------------------
// mma_kernel: 128 CTAs x 544 threads.
//   warps 0-15: consumers (warp tile 16x64, register A via HMUL2)
//   warp 16:    producer (cp.async.bulk through 4-stage mbarrier ring)
// NO CTA-wide barrier in the mainloop; 4 consumer warps per SMSP.
// ---------------------------------------------------------------------------
#define SIM_OFF 0                       // 128*33 f32 = 16896
#define MB_OFF  16896                   // full[4] @ +0, empty[4] @ +32
#define KM_OFF  17024                   // 32*65 f32 + 32 f32 = 8448
#define KS_OFF  25472                   // 128*64 f32 = 32768 (prologue scratch)
#define B_OFF   58368                   // 4 x 32768
#define SMEM_BYTES 189440

__device__ __forceinline__ void mma16816(float* c, const uint32_t* a,
                                         uint32_t b0, uint32_t b1) {
    asm volatile(
        "mma.sync.aligned.m16n8k16.row.col.f32.f16.f16.f32 "
        "{%0,%1,%2,%3}, {%4,%5,%6,%7}, {%8,%9}, {%0,%1,%2,%3};"
        : "+f"(c[0]), "+f"(c[1]), "+f"(c[2]), "+f"(c[3])
        : "r"(a[0]), "r"(a[1]), "r"(a[2]), "r"(a[3]), "r"(b0), "r"(b1));
}

__global__ __launch_bounds__(NTHR, 1) void mma_kernel(const float* __restrict__ x,
                                                      const float* __restrict__ key,
                                                      const float* __restrict__ sens,
                                                      const float* __restrict__ keys_map,
                                                      float* __restrict__ out)
{
    extern __shared__ __align__(16) unsigned char sm[];
    float* simS = (float*)(sm + SIM_OFF);    // [row][m] stride 33

    uint32_t smb;
    asm("{ .reg .u64 t; cvta.to.shared.u64 t, %1; cvt.u32.u64 %0, t; }"
        : "=r"(smb) : "l"(sm));
    uint64_t gb;
    {
        const unsigned char* p = g_Bf;
        asm("cvta.to.global.u64 %0, %1;" : "=l"(gb) : "l"(p));
    }

    const int tid = threadIdx.x;
    const int l = tid & 31, w = tid >> 5;
    const int g = l >> 2, t = l & 3;
    const int row0 = blockIdx.x * TB;

    const uint32_t mb_full  = smb + MB_OFF;       // +8*s
    const uint32_t mb_empty = smb + MB_OFF + 32;  // +8*s

    if (tid == 0) {
        #pragma unroll
        for (int s = 0; s < NSTAGE; s++) {
            mbar_init(mb_full + 8 * s, 1);
            mbar_init(mb_empty + 8 * s, NCONS);
        }
    }
    {
        float* kmS = (float*)(sm + KM_OFF);
        float* ssS = kmS + 32 * 65;
        float* ksS = (float*)(sm + KS_OFF);
        for (int i = tid; i < NM * NKEY; i += NTHR)
            kmS[(i >> 6) * 65 + (i & 63)] = keys_map[i];
        for (int i = tid; i < TB * NKEY; i += NTHR)
            ksS[i] = key[(size_t)row0 * NKEY + i];
        if (tid < NM) ssS[tid] = sens[tid];
    }
    __syncthreads();   // mbarriers + scratch visible; last CTA-wide barrier

    if (w == NCONS) {
        // ------------------------------ producer ------------------------------
        if (l == 0) {
            #pragma unroll 1
            for (int c = 0; c < NCH; c++) {
                const int s = c & 3;
                const uint32_t u = (uint32_t)(c >> 2);
                mbar_wait(mb_empty + 8 * s, (u & 1u) ^ 1u);
                mbar_expect_tx(mb_full + 8 * s, CHB);
                bulk_copy(smb + B_OFF + s * 32768, gb + (uint64_t)c * CHB,
                          CHB, mb_full + 8 * s);
            }
        }
        return;
    }

    // ------------------------------ consumers ------------------------------
    const int rg = w >> 1, cg = w & 1;               // warp tile 16x64
    const int r0 = rg * 16 + g;                      // this thread's 2 A rows
    const int r1 = r0 + 8;

    // ---- x -> registers as half2, fragment slot order (2 rows) ----
    __half2 xh[2][8][2];
    {
        const float* x0 = x + (size_t)(row0 + r0) * ND;
        const float* x1 = x + (size_t)(row0 + r1) * ND;
        #pragma unroll
        for (int j = 0; j < 8; j++) {
            const int k0 = j * 16 + 2 * t;
            float2 v0 = __ldg((const float2*)(x0 + k0));
            float2 v1 = __ldg((const float2*)(x0 + k0 + 8));
            float2 v2 = __ldg((const float2*)(x1 + k0));
            float2 v3 = __ldg((const float2*)(x1 + k0 + 8));
            xh[0][j][0] = __floats2half2_rn(v0.x, v0.y);
            xh[0][j][1] = __floats2half2_rn(v1.x, v1.y);
            xh[1][j][0] = __floats2half2_rn(v2.x, v2.y);
            xh[1][j][1] = __floats2half2_rn(v3.x, v3.y);
        }
    }

    // ---- sim for this CTA's 128 rows (consumer warp w -> rows w*8..w*8+7) ----
    {
        const float* kmS = (const float*)(sm + KM_OFF);
        const float* ssS = kmS + 32 * 65;
        const float* ksS = (const float*)(sm + KS_OFF);
        const int m = l;
        #pragma unroll 1
        for (int i = 0; i < 8; i++) {
            const int r = w * 8 + i;
            float d2 = 0.f;
            #pragma unroll
            for (int k = 0; k < NKEY; k++) {
                const float df = ksS[r * 64 + k] - kmS[m * 65 + k];
                d2 = fmaf(df, df, d2);
            }
            const float lg = ssS[m] / (sqrtf(d2) + 1.0f);
            float mx = lg;
            #pragma unroll
            for (int o = 16; o > 0; o >>= 1)
                mx = fmaxf(mx, __shfl_xor_sync(0xFFFFFFFFu, mx, o));
            const float e = __expf(lg - mx);
            float s = e;
            #pragma unroll
            for (int o = 16; o > 0; o >>= 1)
                s += __shfl_xor_sync(0xFFFFFFFFu, s, o);
            simS[r * 33 + m] = e / s;
        }
    }
    // consumer-only barrier (producer is busy in its own loop)
    asm volatile("bar.sync 1, %0;" :: "n"(NCONS * 32) : "memory");

    float acc[8][4];
    #pragma unroll
    for (int nf = 0; nf < 8; nf++)
        #pragma unroll
        for (int i = 0; i < 4; i++) acc[nf][i] = 0.f;

    // ---- mainloop: 32 weight chunks, decoupled warps ----
    #pragma unroll 1
    for (int c = 0; c < 32; c++) {
        const int s = c & 3;
        const uint32_t u = (uint32_t)(c >> 2);
        mbar_wait(mb_full + 8 * s, u & 1u);

        const __half2 sh0 = __float2half2_rn(simS[r0 * 33 + c]);
        const __half2 sh1 = __float2half2_rn(simS[r1 * 33 + c]);

        const uint4* bbb = (const uint4*)(sm + B_OFF + s * 32768);
        #pragma unroll
        for (int ksn = 0; ksn < 8; ksn++) {
            __half2 f;
            uint32_t a0[4];
            f = __hmul2(sh0, xh[0][ksn][0]); a0[0] = *(uint32_t*)&f;
            f = __hmul2(sh1, xh[1][ksn][0]); a0[1] = *(uint32_t*)&f;
            f = __hmul2(sh0, xh[0][ksn][1]); a0[2] = *(uint32_t*)&f;
            f = __hmul2(sh1, xh[1][ksn][1]); a0[3] = *(uint32_t*)&f;
            #pragma unroll
            for (int nf2 = 0; nf2 < 4; nf2++) {
                uint4 Bp = bbb[(ksn * 8 + cg * 4 + nf2) * 32 + l];
                mma16816(acc[2*nf2+0], a0, Bp.x, Bp.y);
                mma16816(acc[2*nf2+1], a0, Bp.z, Bp.w);
            }
        }

        __syncwarp();
        if (l == 0) mbar_arrive(mb_empty + 8 * s);
    }

    // ---- bias chunk c=32 (stage 0): A = sim over k<32 ----
    {
        mbar_wait(mb_full + 0, 0u);   // u=8 -> parity 0
        const uint4* bbb = (const uint4*)(sm + B_OFF);
        #pragma unroll
        for (int ksn = 0; ksn < 2; ksn++) {
            const int k0 = ksn * 16 + 2 * t;
            __half2 f;
            uint32_t a0[4];
            f = __floats2half2_rn(simS[r0*33 + k0],   simS[r0*33 + k0+1]); a0[0] = *(uint32_t*)&f;
            f = __floats2half2_rn(simS[r1*33 + k0],   simS[r1*33 + k0+1]); a0[1] = *(uint32_t*)&f;
            f = __floats2half2_rn(simS[r0*33 + k0+8], simS[r0*33 + k0+9]); a0[2] = *(uint32_t*)&f;
            f = __floats2half2_rn(simS[r1*33 + k0+8], simS[r1*33 + k0+9]); a0[3] = *(uint32_t*)&f;
            #pragma unroll
            for (int nf2 = 0; nf2 < 4; nf2++) {
                uint4 Bp = bbb[(ksn * 8 + cg * 4 + nf2) * 32 + l];
                mma16816(acc[2*nf2+0], a0, Bp.x, Bp.y);
                mma16816(acc[2*nf2+1], a0, Bp.z, Bp.w);
            }
        }
    }

    // ---- epilogue (1/32 already folded into B) ----
    {
        const int ra = row0 + r0, rb2 = row0 + r1;
        #pragma unroll
        for (int nf = 0; nf < 8; nf++) {
            const int col = cg * 64 + nf * 8 + 2 * t;
            float2 v0, v1;
            v0.x = acc[nf][0]; v0.y = acc[nf][1];
            v1.x = acc[nf][2]; v1.y = acc[nf][3];
            *(float2*)&out[(size_t)ra * NU + col] = v0;
            *(float2*)&out[(size_t)rb2 * NU + col] = v1;
        }
    }
}

// ---------------------------------------------------------------------------
extern "C" void kernel_launch(void* const* d_in, const int* in_sizes, int n_in,
                              void* d_out, int out_size)
{
    const float *key = 0, *x = 0, *sens = 0, *keys_map = 0, *kernels = 0, *biases = 0;
    for (int i = 0; i < n_in; i++) {
        switch (in_sizes[i]) {
            case NB * NKEY:    key      = (const float*)d_in[i]; break;
            case NB * ND:      x        = (const float*)d_in[i]; break;
            case NM:           sens     = (const float*)d_in[i]; break;
            case NM * NKEY:    keys_map = (const float*)d_in[i]; break;
            case NM * ND * NU: kernels  = (const float*)d_in[i]; break;
            case NM * NU:      biases   = (const float*)d_in[i]; break;
            default: break;
        }
    }
    float* out = (float*)d_out;

    cudaFuncSetAttribute(mma_kernel, cudaFuncAttributeMaxDynamicSharedMemorySize,
                         SMEM_BYTES);

    prep_b<<<NCH * 4, 256>>>(kernels, biases);
    mma_kernel<<<NB / TB, NTHR, SMEM_BYTES>>>(x, key, sens, keys_map, out);
}